// round 7
// baseline (speedup 1.0000x reference)
#include <cuda_runtime.h>
#include <cuda_bf16.h>
#include <cstdint>
#include <math.h>

#define HID    4096
#define NHEADS 32
#define HDIM   128
#define BATCH  2
#define SEQ    1024
#define TOKENS 2048
#define H3     12288

// ================= scratch (device globals) =================
__device__ __align__(16) __nv_bfloat16 g_a_hi[(size_t)TOKENS * HID];
__device__ __align__(16) __nv_bfloat16 g_a_lo[(size_t)TOKENS * HID];
__device__ __align__(16) __nv_bfloat16 g_wq_hi[(size_t)H3 * HID];     // qkv_w^T [N,K]
__device__ __align__(16) __nv_bfloat16 g_wq_lo[(size_t)H3 * HID];
__device__ __align__(16) __nv_bfloat16 g_wo_hi[(size_t)HID * HID];    // attn_ow^T [N,K]
__device__ __align__(16) __nv_bfloat16 g_wo_lo[(size_t)HID * HID];
__device__ __align__(16) __nv_bfloat16 g_qkv_hi[(size_t)TOKENS * H3];
__device__ __align__(16) __nv_bfloat16 g_qkv_lo[(size_t)TOKENS * H3];
__device__ __align__(16) __nv_bfloat16 g_vT_hi[(size_t)BATCH * NHEADS * HDIM * SEQ];
__device__ __align__(16) __nv_bfloat16 g_vT_lo[(size_t)BATCH * NHEADS * HDIM * SEQ];
__device__ __align__(16) float g_scores[(size_t)BATCH * NHEADS * SEQ * SEQ];
__device__ __align__(16) __nv_bfloat16 g_p_hi[(size_t)BATCH * NHEADS * SEQ * SEQ];
__device__ __align__(16) __nv_bfloat16 g_p_lo[(size_t)BATCH * NHEADS * SEQ * SEQ];
__device__ __align__(16) __nv_bfloat16 g_c_hi[(size_t)TOKENS * HID];
__device__ __align__(16) __nv_bfloat16 g_c_lo[(size_t)TOKENS * HID];

// ================= helpers =================
__device__ __forceinline__ uint32_t smem_u32(const void* p) {
    uint32_t a;
    asm("{ .reg .u64 t; cvta.to.shared.u64 t, %1; cvt.u32.u64 %0, t; }" : "=r"(a) : "l"(p));
    return a;
}
#define CP16(saddr, gptr) \
    asm volatile("cp.async.cg.shared.global [%0], [%1], 16;" :: "r"(saddr), "l"(gptr) : "memory")
#define CP_COMMIT() asm volatile("cp.async.commit_group;" ::: "memory")
#define CP_WAIT2()  asm volatile("cp.async.wait_group 2;" ::: "memory")
#define LDSM4(r0, r1, r2, r3, addr) \
    asm volatile("ldmatrix.sync.aligned.m8n8.x4.shared.b16 {%0,%1,%2,%3}, [%4];" \
        : "=r"(r0), "=r"(r1), "=r"(r2), "=r"(r3) : "r"(addr))
#define MMA16816(c, a, b0v, b1v) \
    asm volatile("mma.sync.aligned.m16n8k16.row.col.f32.bf16.bf16.f32 " \
        "{%0,%1,%2,%3}, {%4,%5,%6,%7}, {%8,%9}, {%0,%1,%2,%3};" \
        : "+f"((c)[0]), "+f"((c)[1]), "+f"((c)[2]), "+f"((c)[3]) \
        : "r"((a)[0]), "r"((a)[1]), "r"((a)[2]), "r"((a)[3]), "r"(b0v), "r"(b1v))

// ================= HMMA split-bf16 GEMM (3-stage, BK=32, hi|lo packed rows) =================
// C[M,N] = alpha * A[M,K] @ W[N,K]^T (+bias).  SMEM row layout per 32-K chunk:
// 128 bytes = [ hi k0..31 (64B) | lo k0..31 (64B) ], SW128 swizzle on the 128B row.
// Tile: 128 x (64*NG); 8 warps as 2m x 4n, warp tile 64 x (16*NG).
// Batched via blockIdx.z: off = (z>>5)*s?1 + (z&31)*s?2.
// CAUSAL: tile skip above diagonal.  KLIM: K limited to (bm+1)*128 (causal PV).
template<int NG, bool HAS_BIAS, bool SPLIT_OUT, bool CAUSAL, bool KLIM>
__global__ __launch_bounds__(256, 1) void gemm_mma(
    const __nv_bfloat16* __restrict__ Ah, const __nv_bfloat16* __restrict__ Al,
    const __nv_bfloat16* __restrict__ Wh, const __nv_bfloat16* __restrict__ Wl,
    const float* __restrict__ bias,
    float* __restrict__ Cf,
    __nv_bfloat16* __restrict__ Ch, __nv_bfloat16* __restrict__ Cl,
    int K, int lda, int ldb, int ldc,
    long long sA1, long long sA2, long long sB1, long long sB2,
    long long sC1, long long sC2, float alpha)
{
    constexpr int BN    = 64 * NG;
    constexpr int STAGE = 16384 + NG * 8192;   // A 16KB + B NG*8KB
    constexpr int BOFF  = 16384;
    constexpr int P     = (128 + BN) / 32;     // loader passes

    extern __shared__ char smem[];
    const int bm = blockIdx.x, bn = blockIdx.y;
    if (CAUSAL && bn * BN > bm * 128 + 127) return;

    const uint32_t sbase = smem_u32(smem);
    const int tid = threadIdx.x;
    const int wid = tid >> 5, lane = tid & 31;
    const int warp_m = wid >> 2, warp_n = wid & 3;

    const int z = blockIdx.z;
    const long long offA = (long long)(z >> 5) * sA1 + (long long)(z & 31) * sA2;
    const long long offB = (long long)(z >> 5) * sB1 + (long long)(z & 31) * sB2;
    const long long offC = (long long)(z >> 5) * sC1 + (long long)(z & 31) * sC2;

    const __nv_bfloat16* baseAh = Ah + offA + (size_t)bm * 128 * lda;
    const __nv_bfloat16* baseAl = Al + offA + (size_t)bm * 128 * lda;
    const __nv_bfloat16* baseBh = Wh + offB + (size_t)bn * BN * ldb;
    const __nv_bfloat16* baseBl = Wl + offB + (size_t)bn * BN * ldb;

    // loader mapping: thread -> (row_base, unit). unit u<4 = hi half, u>=4 = lo half.
    const int r_base = tid >> 3;
    const int u = tid & 7;
    const int koff_u = (u & 3) * 8;
    const __nv_bfloat16* srcA = (u < 4) ? baseAh : baseAl;
    const __nv_bfloat16* srcB = (u < 4) ? baseBh : baseBl;

#define LOAD_STAGE(st, k0elem) do { \
        const uint32_t _sb = sbase + (uint32_t)(st) * STAGE; \
        _Pragma("unroll") \
        for (int _p = 0; _p < P; _p++) { \
            const int _r = _p * 32 + r_base; \
            const uint32_t _sw = ((uint32_t)u * 16u) ^ (uint32_t)((_r & 7) << 4); \
            if (_r < 128) { \
                CP16(_sb + (uint32_t)_r * 128u + _sw, \
                     srcA + (size_t)_r * lda + (k0elem) + koff_u); \
            } else { \
                const int _rb = _r - 128; \
                CP16(_sb + BOFF + (uint32_t)_rb * 128u + _sw, \
                     srcB + (size_t)_rb * ldb + (k0elem) + koff_u); \
            } \
        } \
    } while (0)

    // ldmatrix lane addressing
    const int lr = lane & 15;
    const uint32_t kb_lane = (uint32_t)(lane >> 4) * 16u;
    uint32_t a_ro[4], a_xm[4];
#pragma unroll
    for (int mb = 0; mb < 4; mb++) {
        const int r = warp_m * 64 + mb * 16 + lr;
        a_ro[mb] = (uint32_t)r * 128u;
        a_xm[mb] = (uint32_t)((r & 7) << 4);
    }
    uint32_t b_ro[NG], b_xm[NG];
#pragma unroll
    for (int g = 0; g < NG; g++) {
        const int r = warp_n * (16 * NG) + g * 16 + lr;
        b_ro[g] = (uint32_t)r * 128u;
        b_xm[g] = (uint32_t)((r & 7) << 4);
    }

    float acc[4][2 * NG][4] = {};

    int Keff = K;
    if (KLIM) { int kl = (bm + 1) * 128; Keff = kl < K ? kl : K; }
    const int NC = Keff / 32;

    LOAD_STAGE(0, 0);  CP_COMMIT();
    LOAD_STAGE(1, 32); CP_COMMIT();

    for (int i = 0; i < NC; i++) {
        if (i + 2 < NC) LOAD_STAGE((i + 2) % 3, (size_t)(i + 2) * 32);
        CP_COMMIT();
        CP_WAIT2();
        __syncthreads();

        const uint32_t sb = sbase + (uint32_t)(i % 3) * STAGE;
#pragma unroll
        for (int ks = 0; ks < 2; ks++) {
            const uint32_t kb = (uint32_t)ks * 32u + kb_lane;   // hi cols; lo = +64
            uint32_t ah[4][4], al[4][4];
#pragma unroll
            for (int mb = 0; mb < 4; mb++) {
                const uint32_t ro = sb + a_ro[mb];
                LDSM4(ah[mb][0], ah[mb][1], ah[mb][2], ah[mb][3], ro + (kb ^ a_xm[mb]));
                LDSM4(al[mb][0], al[mb][1], al[mb][2], al[mb][3], ro + ((kb + 64u) ^ a_xm[mb]));
            }
            uint32_t bh[NG][4], bl[NG][4];
#pragma unroll
            for (int g = 0; g < NG; g++) {
                const uint32_t ro = sb + BOFF + b_ro[g];
                LDSM4(bh[g][0], bh[g][1], bh[g][2], bh[g][3], ro + (kb ^ b_xm[g]));
                LDSM4(bl[g][0], bl[g][1], bl[g][2], bl[g][3], ro + ((kb + 64u) ^ b_xm[g]));
            }
#pragma unroll
            for (int mb = 0; mb < 4; mb++) {
#pragma unroll
                for (int nf = 0; nf < 2 * NG; nf++) {
                    const int g = nf >> 1, j = nf & 1;
                    MMA16816(acc[mb][nf], ah[mb], bh[g][j], bh[g][2 + j]);
                    MMA16816(acc[mb][nf], ah[mb], bl[g][j], bl[g][2 + j]);
                    MMA16816(acc[mb][nf], al[mb], bh[g][j], bh[g][2 + j]);
                }
            }
        }
        __syncthreads();
    }

    // epilogue
    const int qrow = lane >> 2;
    const int qcol = (lane & 3) * 2;
#pragma unroll
    for (int mb = 0; mb < 4; mb++) {
        const int m0 = bm * 128 + warp_m * 64 + mb * 16 + qrow;
#pragma unroll
        for (int nf = 0; nf < 2 * NG; nf++) {
            const int n0 = bn * BN + warp_n * (16 * NG) + nf * 8 + qcol;
            float b0 = 0.f, b1 = 0.f;
            if (HAS_BIAS) { b0 = bias[n0]; b1 = bias[n0 + 1]; }
            float v00 = acc[mb][nf][0] * alpha + b0;
            float v01 = acc[mb][nf][1] * alpha + b1;
            float v10 = acc[mb][nf][2] * alpha + b0;
            float v11 = acc[mb][nf][3] * alpha + b1;
            if (SPLIT_OUT) {
                __nv_bfloat162 h0, l0, h1, l1;
                h0.x = __float2bfloat16(v00);
                h0.y = __float2bfloat16(v01);
                l0.x = __float2bfloat16(v00 - __bfloat162float(h0.x));
                l0.y = __float2bfloat16(v01 - __bfloat162float(h0.y));
                h1.x = __float2bfloat16(v10);
                h1.y = __float2bfloat16(v11);
                l1.x = __float2bfloat16(v10 - __bfloat162float(h1.x));
                l1.y = __float2bfloat16(v11 - __bfloat162float(h1.y));
                *(__nv_bfloat162*)(Ch + offC + (size_t)m0 * ldc + n0)       = h0;
                *(__nv_bfloat162*)(Cl + offC + (size_t)m0 * ldc + n0)       = l0;
                *(__nv_bfloat162*)(Ch + offC + (size_t)(m0 + 8) * ldc + n0) = h1;
                *(__nv_bfloat162*)(Cl + offC + (size_t)(m0 + 8) * ldc + n0) = l1;
            } else {
                float2 r0, r1;
                r0.x = v00; r0.y = v01;
                r1.x = v10; r1.y = v11;
                *(float2*)(Cf + offC + (size_t)m0 * ldc + n0)       = r0;
                *(float2*)(Cf + offC + (size_t)(m0 + 8) * ldc + n0) = r1;
            }
        }
    }
#undef LOAD_STAGE
}

// ================= LayerNorm -> split bf16 =================
__global__ __launch_bounds__(256) void ln_split_kernel(
    const float* __restrict__ x, const float* __restrict__ w,
    const float* __restrict__ bvec,
    __nv_bfloat16* __restrict__ oh, __nv_bfloat16* __restrict__ ol)
{
    int row = blockIdx.x;
    int tid = threadIdx.x;
    const float* xr = x + (size_t)row * HID;
    float4 v[4];
    float sum = 0.f, ss = 0.f;
#pragma unroll
    for (int i = 0; i < 4; i++) {
        v[i] = *(const float4*)(xr + (i * 256 + tid) * 4);
        sum += v[i].x + v[i].y + v[i].z + v[i].w;
        ss  += v[i].x * v[i].x + v[i].y * v[i].y + v[i].z * v[i].z + v[i].w * v[i].w;
    }
#pragma unroll
    for (int off = 16; off > 0; off >>= 1) {
        sum += __shfl_xor_sync(0xffffffffu, sum, off);
        ss  += __shfl_xor_sync(0xffffffffu, ss,  off);
    }
    __shared__ float r0[8], r1[8];
    __shared__ float s_mu, s_rstd;
    int wid = tid >> 5, lane = tid & 31;
    if (lane == 0) { r0[wid] = sum; r1[wid] = ss; }
    __syncthreads();
    if (tid == 0) {
        float s = 0.f, q = 0.f;
        for (int i = 0; i < 8; i++) { s += r0[i]; q += r1[i]; }
        float mu  = s * (1.f / HID);
        float var = q * (1.f / HID) - mu * mu;
        s_mu = mu; s_rstd = rsqrtf(var + 1e-5f);
    }
    __syncthreads();
    float mu = s_mu, rstd = s_rstd;
#pragma unroll
    for (int i = 0; i < 4; i++) {
        int c = (i * 256 + tid) * 4;
        float4 wv = *(const float4*)(w + c);
        float4 bv = *(const float4*)(bvec + c);
        float o[4];
        o[0] = (v[i].x - mu) * rstd * wv.x + bv.x;
        o[1] = (v[i].y - mu) * rstd * wv.y + bv.y;
        o[2] = (v[i].z - mu) * rstd * wv.z + bv.z;
        o[3] = (v[i].w - mu) * rstd * wv.w + bv.w;
        __nv_bfloat16 h[4], l[4];
#pragma unroll
        for (int j = 0; j < 4; j++) {
            h[j] = __float2bfloat16(o[j]);
            l[j] = __float2bfloat16(o[j] - __bfloat162float(h[j]));
        }
        *(uint2*)(oh + (size_t)row * HID + c) = *(uint2*)h;
        *(uint2*)(ol + (size_t)row * HID + c) = *(uint2*)l;
    }
}

// ================= transpose + split: in[K,N] f32 -> out[N,K] bf16 hi/lo =================
__global__ __launch_bounds__(256) void transpose_split_kernel(
    const float* __restrict__ in, __nv_bfloat16* __restrict__ oh,
    __nv_bfloat16* __restrict__ ol, int Kdim, int Ndim)
{
    __shared__ float tile[32][33];
    int n0 = blockIdx.x * 32, k0 = blockIdx.y * 32;
    int tx = threadIdx.x, ty = threadIdx.y;   // block (32,8)
#pragma unroll
    for (int i = 0; i < 32; i += 8)
        tile[ty + i][tx] = in[(size_t)(k0 + ty + i) * Ndim + n0 + tx];
    __syncthreads();
#pragma unroll
    for (int i = 0; i < 32; i += 8) {
        float v = tile[tx][ty + i];
        __nv_bfloat16 h = __float2bfloat16(v);
        size_t idx = (size_t)(n0 + ty + i) * Kdim + k0 + tx;
        oh[idx] = h;
        ol[idx] = __float2bfloat16(v - __bfloat162float(h));
    }
}

// ================= batched bf16 transpose of V: [S,HD] (stride H3) -> [HD,S] =================
__global__ __launch_bounds__(256) void transpose_v_kernel(
    const __nv_bfloat16* __restrict__ qh, const __nv_bfloat16* __restrict__ ql,
    __nv_bfloat16* __restrict__ vth, __nv_bfloat16* __restrict__ vtl)
{
    __shared__ __nv_bfloat16 th[32][33];
    __shared__ __nv_bfloat16 tl[32][33];
    int z = blockIdx.z;
    int b = z >> 5, h = z & 31;
    const size_t in_off  = (size_t)b * SEQ * H3 + 2 * HID + (size_t)h * HDIM;
    const size_t out_off = (size_t)z * HDIM * SEQ;
    int k0 = blockIdx.x * 32;   // token dim
    int d0 = blockIdx.y * 32;   // head dim
    int tx = threadIdx.x, ty = threadIdx.y;  // (32, 8)
#pragma unroll
    for (int i = 0; i < 32; i += 8) {
        size_t src = in_off + (size_t)(k0 + ty + i) * H3 + d0 + tx;
        th[ty + i][tx] = qh[src];
        tl[ty + i][tx] = ql[src];
    }
    __syncthreads();
#pragma unroll
    for (int i = 0; i < 32; i += 8) {
        size_t dst = out_off + (size_t)(d0 + ty + i) * SEQ + k0 + tx;
        vth[dst] = th[tx][ty + i];
        vtl[dst] = tl[tx][ty + i];
    }
}

// ================= causal softmax: fp32 scores -> split bf16 P =================
__global__ __launch_bounds__(256) void softmax_kernel(
    const float* __restrict__ scores, const float* __restrict__ mask,
    __nv_bfloat16* __restrict__ ph, __nv_bfloat16* __restrict__ pl)
{
    int q = blockIdx.x, h = blockIdx.y, b = blockIdx.z;
    const size_t rowoff = (((size_t)(b * NHEADS + h) * SEQ + q) * SEQ);
    const float* row = scores + rowoff;
    int tid = threadIdx.x;
    int c0 = tid * 4;

    float4 v  = *(const float4*)(row + c0);
    float4 mk = *(const float4*)(mask + b * SEQ + c0);
    float vals[4] = {v.x + mk.x, v.y + mk.y, v.z + mk.z, v.w + mk.w};
#pragma unroll
    for (int j = 0; j < 4; j++)
        if (c0 + j > q) vals[j] = -30000.0f;   // constant: robust to unwritten tiles

    float m = fmaxf(fmaxf(vals[0], vals[1]), fmaxf(vals[2], vals[3]));
#pragma unroll
    for (int off = 16; off > 0; off >>= 1)
        m = fmaxf(m, __shfl_xor_sync(0xffffffffu, m, off));

    __shared__ float rmax[8], rsum[8];
    __shared__ float s_max, s_inv;
    int wid = tid >> 5, lane = tid & 31;
    if (lane == 0) rmax[wid] = m;
    __syncthreads();
    if (tid == 0) {
        float t = rmax[0];
        for (int i = 1; i < 8; i++) t = fmaxf(t, rmax[i]);
        s_max = t;
    }
    __syncthreads();
    float rowmax = s_max;

    float e[4], sum = 0.f;
#pragma unroll
    for (int j = 0; j < 4; j++) { e[j] = __expf(vals[j] - rowmax); sum += e[j]; }
#pragma unroll
    for (int off = 16; off > 0; off >>= 1)
        sum += __shfl_xor_sync(0xffffffffu, sum, off);
    if (lane == 0) rsum[wid] = sum;
    __syncthreads();
    if (tid == 0) {
        float t = 0.f;
        for (int i = 0; i < 8; i++) t += rsum[i];
        s_inv = 1.f / t;
    }
    __syncthreads();
    float inv = s_inv;

    __nv_bfloat16 hh[4], ll[4];
#pragma unroll
    for (int j = 0; j < 4; j++) {
        float p = e[j] * inv;
        hh[j] = __float2bfloat16(p);
        ll[j] = __float2bfloat16(p - __bfloat162float(hh[j]));
    }
    *(uint2*)(ph + rowoff + c0) = *(uint2*)hh;
    *(uint2*)(pl + rowoff + c0) = *(uint2*)ll;
}

// ================= launch =================
#define SMEM_NG4 (3 * (16384 + 4 * 8192))   // 147456
#define SMEM_NG2 (3 * (16384 + 2 * 8192))   //  98304

extern "C" void kernel_launch(void* const* d_in, const int* in_sizes, int n_in,
                              void* d_out, int out_size)
{
    const float* x       = (const float*)d_in[0];
    const float* mask    = (const float*)d_in[1];
    const float* norm_w  = (const float*)d_in[2];
    const float* norm_b  = (const float*)d_in[3];
    const float* qkv_w   = (const float*)d_in[4];
    const float* qkv_b   = (const float*)d_in[5];
    const float* attn_ow = (const float*)d_in[6];
    float* out = (float*)d_out;

    __nv_bfloat16 *p_ah, *p_al, *p_wqh, *p_wql, *p_woh, *p_wol;
    __nv_bfloat16 *p_qh, *p_ql, *p_vth, *p_vtl, *p_ph, *p_pl, *p_ch, *p_cl;
    float *p_scores;
    cudaGetSymbolAddress((void**)&p_ah,  g_a_hi);
    cudaGetSymbolAddress((void**)&p_al,  g_a_lo);
    cudaGetSymbolAddress((void**)&p_wqh, g_wq_hi);
    cudaGetSymbolAddress((void**)&p_wql, g_wq_lo);
    cudaGetSymbolAddress((void**)&p_woh, g_wo_hi);
    cudaGetSymbolAddress((void**)&p_wol, g_wo_lo);
    cudaGetSymbolAddress((void**)&p_qh,  g_qkv_hi);
    cudaGetSymbolAddress((void**)&p_ql,  g_qkv_lo);
    cudaGetSymbolAddress((void**)&p_vth, g_vT_hi);
    cudaGetSymbolAddress((void**)&p_vtl, g_vT_lo);
    cudaGetSymbolAddress((void**)&p_ph,  g_p_hi);
    cudaGetSymbolAddress((void**)&p_pl,  g_p_lo);
    cudaGetSymbolAddress((void**)&p_ch,  g_c_hi);
    cudaGetSymbolAddress((void**)&p_cl,  g_c_lo);
    cudaGetSymbolAddress((void**)&p_scores, g_scores);

    cudaFuncSetAttribute((const void*)gemm_mma<4, true,  true,  false, false>, cudaFuncAttributeMaxDynamicSharedMemorySize, SMEM_NG4);
    cudaFuncSetAttribute((const void*)gemm_mma<4, false, false, true,  false>, cudaFuncAttributeMaxDynamicSharedMemorySize, SMEM_NG4);
    cudaFuncSetAttribute((const void*)gemm_mma<2, false, true,  false, true >, cudaFuncAttributeMaxDynamicSharedMemorySize, SMEM_NG2);
    cudaFuncSetAttribute((const void*)gemm_mma<4, false, false, false, false>, cudaFuncAttributeMaxDynamicSharedMemorySize, SMEM_NG4);

    const float inv_sqrt_hd = 0.08838834764831845f;  // 1/sqrt(128)

    // 1) LayerNorm -> split bf16 activations
    ln_split_kernel<<<TOKENS, 256>>>(x, norm_w, norm_b, p_ah, p_al);

    // 2) weight transpose+split to [N,K] bf16 hi/lo
    transpose_split_kernel<<<dim3(H3 / 32, HID / 32), dim3(32, 8)>>>(qkv_w, p_wqh, p_wql, HID, H3);
    transpose_split_kernel<<<dim3(HID / 32, HID / 32), dim3(32, 8)>>>(attn_ow, p_woh, p_wol, HID, HID);

    // 3) QKV GEMM + bias -> split bf16 qkv  (tile 128x256)
    gemm_mma<4, true, true, false, false><<<dim3(TOKENS / 128, H3 / 256), 256, SMEM_NG4>>>(
        p_ah, p_al, p_wqh, p_wql, qkv_b, nullptr, p_qh, p_ql,
        HID, HID, HID, H3,
        0, 0, 0, 0, 0, 0, 1.0f);

    // 4) transpose V -> vT [z][HD][S]
    transpose_v_kernel<<<dim3(SEQ / 32, HDIM / 32, BATCH * NHEADS), dim3(32, 8)>>>(
        p_qh, p_ql, p_vth, p_vtl);

    // 5) scores = Q @ K^T * 1/sqrt(hd), causal tile skip, fp32 out (tile 128x256)
    gemm_mma<4, false, false, true, false><<<dim3(SEQ / 128, SEQ / 256, BATCH * NHEADS), 256, SMEM_NG4>>>(
        p_qh, p_ql, p_qh + HID, p_ql + HID, nullptr, p_scores, nullptr, nullptr,
        HDIM, H3, H3, SEQ,
        (long long)SEQ * H3, HDIM,
        (long long)SEQ * H3, HDIM,
        (long long)NHEADS * SEQ * SEQ, (long long)SEQ * SEQ,
        inv_sqrt_hd);

    // 6) softmax -> split bf16 P
    softmax_kernel<<<dim3(SEQ, NHEADS, BATCH), 256>>>(p_scores, mask, p_ph, p_pl);

    // 7) ctx = P @ V  (B = vT [HD,S]); causal K-limit; split bf16 out (tile 128x128)
    gemm_mma<2, false, true, false, true><<<dim3(SEQ / 128, HDIM / 128, BATCH * NHEADS), 256, SMEM_NG2>>>(
        p_ph, p_pl, p_vth, p_vtl, nullptr, nullptr, p_ch, p_cl,
        SEQ, SEQ, SEQ, HID,
        (long long)NHEADS * SEQ * SEQ, (long long)SEQ * SEQ,
        (long long)NHEADS * HDIM * SEQ, (long long)HDIM * SEQ,
        (long long)SEQ * HID, HDIM,
        1.0f);

    // 8) out = ctx @ attn_ow, fp32  (tile 128x256)
    gemm_mma<4, false, false, false, false><<<dim3(TOKENS / 128, HID / 256), 256, SMEM_NG4>>>(
        p_ch, p_cl, p_woh, p_wol, nullptr, out, nullptr, nullptr,
        HID, HID, HID, HID,
        0, 0, 0, 0, 0, 0, 1.0f);
}

// round 8
// speedup vs baseline: 1.0816x; 1.0816x over previous
#include <cuda_runtime.h>
#include <cuda_bf16.h>
#include <cstdint>
#include <math.h>

#define HID    4096
#define NHEADS 32
#define HDIM   128
#define BATCH  2
#define SEQ    1024
#define TOKENS 2048
#define H3     12288

// ================= scratch (device globals) =================
__device__ __align__(16) __nv_bfloat16 g_a_hi[(size_t)TOKENS * HID];
__device__ __align__(16) __nv_bfloat16 g_a_lo[(size_t)TOKENS * HID];
__device__ __align__(16) __nv_bfloat16 g_wq_hi[(size_t)H3 * HID];     // qkv_w^T [N,K]
__device__ __align__(16) __nv_bfloat16 g_wq_lo[(size_t)H3 * HID];
__device__ __align__(16) __nv_bfloat16 g_wo_hi[(size_t)HID * HID];    // attn_ow^T [N,K]
__device__ __align__(16) __nv_bfloat16 g_wo_lo[(size_t)HID * HID];
__device__ __align__(16) __nv_bfloat16 g_qkv_hi[(size_t)TOKENS * H3];
__device__ __align__(16) __nv_bfloat16 g_qkv_lo[(size_t)TOKENS * H3];
__device__ __align__(16) __nv_bfloat16 g_vT_hi[(size_t)BATCH * NHEADS * HDIM * SEQ];
__device__ __align__(16) __nv_bfloat16 g_vT_lo[(size_t)BATCH * NHEADS * HDIM * SEQ];
__device__ __align__(16) float g_scores[(size_t)BATCH * NHEADS * SEQ * SEQ];
__device__ __align__(16) __nv_bfloat16 g_p_hi[(size_t)BATCH * NHEADS * SEQ * SEQ];
__device__ __align__(16) __nv_bfloat16 g_p_lo[(size_t)BATCH * NHEADS * SEQ * SEQ];
__device__ __align__(16) __nv_bfloat16 g_c_hi[(size_t)TOKENS * HID];
__device__ __align__(16) __nv_bfloat16 g_c_lo[(size_t)TOKENS * HID];

// ================= helpers =================
__device__ __forceinline__ uint32_t smem_u32(const void* p) {
    uint32_t a;
    asm("{ .reg .u64 t; cvta.to.shared.u64 t, %1; cvt.u32.u64 %0, t; }" : "=r"(a) : "l"(p));
    return a;
}
#define CP16(saddr, gptr) \
    asm volatile("cp.async.cg.shared.global [%0], [%1], 16;" :: "r"(saddr), "l"(gptr) : "memory")
#define CP_COMMIT() asm volatile("cp.async.commit_group;" ::: "memory")
#define CP_WAIT2()  asm volatile("cp.async.wait_group 2;" ::: "memory")
#define LDSM4(r0, r1, r2, r3, addr) \
    asm volatile("ldmatrix.sync.aligned.m8n8.x4.shared.b16 {%0,%1,%2,%3}, [%4];" \
        : "=r"(r0), "=r"(r1), "=r"(r2), "=r"(r3) : "r"(addr))
#define MMA16816(c, a, b0v, b1v) \
    asm volatile("mma.sync.aligned.m16n8k16.row.col.f32.bf16.bf16.f32 " \
        "{%0,%1,%2,%3}, {%4,%5,%6,%7}, {%8,%9}, {%0,%1,%2,%3};" \
        : "+f"((c)[0]), "+f"((c)[1]), "+f"((c)[2]), "+f"((c)[3]) \
        : "r"((a)[0]), "r"((a)[1]), "r"((a)[2]), "r"((a)[3]), "r"(b0v), "r"(b1v))

// ================= HMMA split-bf16 GEMM (3-stage, BK=32, hi|lo packed rows) =================
// C[M,N] = alpha * A[M,K] @ W[N,K]^T (+bias).  SMEM row layout per 32-K chunk:
// 128 bytes = [ hi k0..31 (64B) | lo k0..31 (64B) ], SW128 swizzle on the 128B row.
// Tile: 128 x 128; 8 warps as 2m x 4n, warp tile 64 x 32.  regs<=128 -> 2 CTAs/SM.
// Batched via blockIdx.z: off = (z>>5)*s?1 + (z&31)*s?2.
// CAUSAL: tile skip above diagonal.  KLIM: K limited to (bm+1)*128 (causal PV).
#define GM_STAGE 32768
#define GM_BOFF  16384
#define GM_SMEM  (3 * GM_STAGE)   // 98304; 2 CTAs/SM (192KB of 228KB)

template<bool HAS_BIAS, bool SPLIT_OUT, bool CAUSAL, bool KLIM>
__global__ __launch_bounds__(256, 2) void gemm_mma(
    const __nv_bfloat16* __restrict__ Ah, const __nv_bfloat16* __restrict__ Al,
    const __nv_bfloat16* __restrict__ Wh, const __nv_bfloat16* __restrict__ Wl,
    const float* __restrict__ bias,
    float* __restrict__ Cf,
    __nv_bfloat16* __restrict__ Ch, __nv_bfloat16* __restrict__ Cl,
    int K, int lda, int ldb, int ldc,
    long long sA1, long long sA2, long long sB1, long long sB2,
    long long sC1, long long sC2, float alpha)
{
    extern __shared__ char smem[];
    const int bm = blockIdx.x, bn = blockIdx.y;
    if (CAUSAL && bn > bm) return;

    const uint32_t sbase = smem_u32(smem);
    const int tid = threadIdx.x;
    const int wid = tid >> 5, lane = tid & 31;
    const int warp_m = wid >> 2, warp_n = wid & 3;

    const int z = blockIdx.z;
    const long long offA = (long long)(z >> 5) * sA1 + (long long)(z & 31) * sA2;
    const long long offB = (long long)(z >> 5) * sB1 + (long long)(z & 31) * sB2;
    const long long offC = (long long)(z >> 5) * sC1 + (long long)(z & 31) * sC2;

    const __nv_bfloat16* baseAh = Ah + offA + (size_t)bm * 128 * lda;
    const __nv_bfloat16* baseAl = Al + offA + (size_t)bm * 128 * lda;
    const __nv_bfloat16* baseBh = Wh + offB + (size_t)bn * 128 * ldb;
    const __nv_bfloat16* baseBl = Wl + offB + (size_t)bn * 128 * ldb;

    // loader mapping: thread -> (row_base, unit). unit u<4 = hi half, u>=4 = lo half.
    const int r_base = tid >> 3;
    const int u = tid & 7;
    const int koff_u = (u & 3) * 8;
    const __nv_bfloat16* srcA = (u < 4) ? baseAh : baseAl;
    const __nv_bfloat16* srcB = (u < 4) ? baseBh : baseBl;
    const uint32_t sw_u = ((uint32_t)u * 16u);

#define LOAD_STAGE(st, k0elem) do { \
        const uint32_t _sb = sbase + (uint32_t)(st) * GM_STAGE; \
        _Pragma("unroll") \
        for (int _p = 0; _p < 4; _p++) { \
            const int _r = _p * 32 + r_base; \
            const uint32_t _sw = sw_u ^ (uint32_t)((_r & 7) << 4); \
            CP16(_sb + (uint32_t)_r * 128u + _sw, \
                 srcA + (size_t)_r * lda + (k0elem) + koff_u); \
            CP16(_sb + GM_BOFF + (uint32_t)_r * 128u + _sw, \
                 srcB + (size_t)_r * ldb + (k0elem) + koff_u); \
        } \
    } while (0)

    // ldmatrix lane addressing
    const int lr = lane & 15;
    const uint32_t kb_lane = (uint32_t)(lane >> 4) * 16u;
    uint32_t a_ro[4], a_xm[4];
#pragma unroll
    for (int mb = 0; mb < 4; mb++) {
        const int r = warp_m * 64 + mb * 16 + lr;
        a_ro[mb] = (uint32_t)r * 128u;
        a_xm[mb] = (uint32_t)((r & 7) << 4);
    }
    uint32_t b_ro[2], b_xm[2];
#pragma unroll
    for (int g = 0; g < 2; g++) {
        const int r = warp_n * 32 + g * 16 + lr;
        b_ro[g] = (uint32_t)r * 128u;
        b_xm[g] = (uint32_t)((r & 7) << 4);
    }

    float acc[4][4][4] = {};

    int Keff = K;
    if (KLIM) { int kl = (bm + 1) * 128; Keff = kl < K ? kl : K; }
    const int NC = Keff / 32;

    LOAD_STAGE(0, 0);  CP_COMMIT();
    LOAD_STAGE(1, 32); CP_COMMIT();

    for (int i = 0; i < NC; i++) {
        if (i + 2 < NC) LOAD_STAGE((i + 2) % 3, (size_t)(i + 2) * 32);
        CP_COMMIT();
        CP_WAIT2();
        __syncthreads();

        const uint32_t sb = sbase + (uint32_t)(i % 3) * GM_STAGE;
#pragma unroll
        for (int ks = 0; ks < 2; ks++) {
            const uint32_t kb = (uint32_t)ks * 32u + kb_lane;   // hi cols; lo = +64
            uint32_t ah[4][4], al[4][4];
#pragma unroll
            for (int mb = 0; mb < 4; mb++) {
                const uint32_t ro = sb + a_ro[mb];
                LDSM4(ah[mb][0], ah[mb][1], ah[mb][2], ah[mb][3], ro + (kb ^ a_xm[mb]));
                LDSM4(al[mb][0], al[mb][1], al[mb][2], al[mb][3], ro + ((kb + 64u) ^ a_xm[mb]));
            }
            uint32_t bh[2][4], bl[2][4];
#pragma unroll
            for (int g = 0; g < 2; g++) {
                const uint32_t ro = sb + GM_BOFF + b_ro[g];
                LDSM4(bh[g][0], bh[g][1], bh[g][2], bh[g][3], ro + (kb ^ b_xm[g]));
                LDSM4(bl[g][0], bl[g][1], bl[g][2], bl[g][3], ro + ((kb + 64u) ^ b_xm[g]));
            }
#pragma unroll
            for (int mb = 0; mb < 4; mb++) {
#pragma unroll
                for (int nf = 0; nf < 4; nf++) {
                    const int g = nf >> 1, j = nf & 1;
                    MMA16816(acc[mb][nf], ah[mb], bh[g][j], bh[g][2 + j]);
                    MMA16816(acc[mb][nf], ah[mb], bl[g][j], bl[g][2 + j]);
                    MMA16816(acc[mb][nf], al[mb], bh[g][j], bh[g][2 + j]);
                }
            }
        }
        __syncthreads();
    }

    // epilogue
    const int qrow = lane >> 2;
    const int qcol = (lane & 3) * 2;
#pragma unroll
    for (int mb = 0; mb < 4; mb++) {
        const int m0 = bm * 128 + warp_m * 64 + mb * 16 + qrow;
#pragma unroll
        for (int nf = 0; nf < 4; nf++) {
            const int n0 = bn * 128 + warp_n * 32 + nf * 8 + qcol;
            float b0 = 0.f, b1 = 0.f;
            if (HAS_BIAS) { b0 = bias[n0]; b1 = bias[n0 + 1]; }
            float v00 = acc[mb][nf][0] * alpha + b0;
            float v01 = acc[mb][nf][1] * alpha + b1;
            float v10 = acc[mb][nf][2] * alpha + b0;
            float v11 = acc[mb][nf][3] * alpha + b1;
            if (SPLIT_OUT) {
                __nv_bfloat162 h0, l0, h1, l1;
                h0.x = __float2bfloat16(v00);
                h0.y = __float2bfloat16(v01);
                l0.x = __float2bfloat16(v00 - __bfloat162float(h0.x));
                l0.y = __float2bfloat16(v01 - __bfloat162float(h0.y));
                h1.x = __float2bfloat16(v10);
                h1.y = __float2bfloat16(v11);
                l1.x = __float2bfloat16(v10 - __bfloat162float(h1.x));
                l1.y = __float2bfloat16(v11 - __bfloat162float(h1.y));
                *(__nv_bfloat162*)(Ch + offC + (size_t)m0 * ldc + n0)       = h0;
                *(__nv_bfloat162*)(Cl + offC + (size_t)m0 * ldc + n0)       = l0;
                *(__nv_bfloat162*)(Ch + offC + (size_t)(m0 + 8) * ldc + n0) = h1;
                *(__nv_bfloat162*)(Cl + offC + (size_t)(m0 + 8) * ldc + n0) = l1;
            } else {
                float2 r0, r1;
                r0.x = v00; r0.y = v01;
                r1.x = v10; r1.y = v11;
                *(float2*)(Cf + offC + (size_t)m0 * ldc + n0)       = r0;
                *(float2*)(Cf + offC + (size_t)(m0 + 8) * ldc + n0) = r1;
            }
        }
    }
#undef LOAD_STAGE
}

// ================= LayerNorm -> split bf16 =================
__global__ __launch_bounds__(256) void ln_split_kernel(
    const float* __restrict__ x, const float* __restrict__ w,
    const float* __restrict__ bvec,
    __nv_bfloat16* __restrict__ oh, __nv_bfloat16* __restrict__ ol)
{
    int row = blockIdx.x;
    int tid = threadIdx.x;
    const float* xr = x + (size_t)row * HID;
    float4 v[4];
    float sum = 0.f, ss = 0.f;
#pragma unroll
    for (int i = 0; i < 4; i++) {
        v[i] = *(const float4*)(xr + (i * 256 + tid) * 4);
        sum += v[i].x + v[i].y + v[i].z + v[i].w;
        ss  += v[i].x * v[i].x + v[i].y * v[i].y + v[i].z * v[i].z + v[i].w * v[i].w;
    }
#pragma unroll
    for (int off = 16; off > 0; off >>= 1) {
        sum += __shfl_xor_sync(0xffffffffu, sum, off);
        ss  += __shfl_xor_sync(0xffffffffu, ss,  off);
    }
    __shared__ float r0[8], r1[8];
    __shared__ float s_mu, s_rstd;
    int wid = tid >> 5, lane = tid & 31;
    if (lane == 0) { r0[wid] = sum; r1[wid] = ss; }
    __syncthreads();
    if (tid == 0) {
        float s = 0.f, q = 0.f;
        for (int i = 0; i < 8; i++) { s += r0[i]; q += r1[i]; }
        float mu  = s * (1.f / HID);
        float var = q * (1.f / HID) - mu * mu;
        s_mu = mu; s_rstd = rsqrtf(var + 1e-5f);
    }
    __syncthreads();
    float mu = s_mu, rstd = s_rstd;
#pragma unroll
    for (int i = 0; i < 4; i++) {
        int c = (i * 256 + tid) * 4;
        float4 wv = *(const float4*)(w + c);
        float4 bv = *(const float4*)(bvec + c);
        float o[4];
        o[0] = (v[i].x - mu) * rstd * wv.x + bv.x;
        o[1] = (v[i].y - mu) * rstd * wv.y + bv.y;
        o[2] = (v[i].z - mu) * rstd * wv.z + bv.z;
        o[3] = (v[i].w - mu) * rstd * wv.w + bv.w;
        __nv_bfloat16 h[4], l[4];
#pragma unroll
        for (int j = 0; j < 4; j++) {
            h[j] = __float2bfloat16(o[j]);
            l[j] = __float2bfloat16(o[j] - __bfloat162float(h[j]));
        }
        *(uint2*)(oh + (size_t)row * HID + c) = *(uint2*)h;
        *(uint2*)(ol + (size_t)row * HID + c) = *(uint2*)l;
    }
}

// ================= transpose + split: in[K,N] f32 -> out[N,K] bf16 hi/lo =================
__global__ __launch_bounds__(256) void transpose_split_kernel(
    const float* __restrict__ in, __nv_bfloat16* __restrict__ oh,
    __nv_bfloat16* __restrict__ ol, int Kdim, int Ndim)
{
    __shared__ float tile[32][33];
    int n0 = blockIdx.x * 32, k0 = blockIdx.y * 32;
    int tx = threadIdx.x, ty = threadIdx.y;   // block (32,8)
#pragma unroll
    for (int i = 0; i < 32; i += 8)
        tile[ty + i][tx] = in[(size_t)(k0 + ty + i) * Ndim + n0 + tx];
    __syncthreads();
#pragma unroll
    for (int i = 0; i < 32; i += 8) {
        float v = tile[tx][ty + i];
        __nv_bfloat16 h = __float2bfloat16(v);
        size_t idx = (size_t)(n0 + ty + i) * Kdim + k0 + tx;
        oh[idx] = h;
        ol[idx] = __float2bfloat16(v - __bfloat162float(h));
    }
}

// ================= batched bf16 transpose of V: [S,HD] (stride H3) -> [HD,S] =================
__global__ __launch_bounds__(256) void transpose_v_kernel(
    const __nv_bfloat16* __restrict__ qh, const __nv_bfloat16* __restrict__ ql,
    __nv_bfloat16* __restrict__ vth, __nv_bfloat16* __restrict__ vtl)
{
    __shared__ __nv_bfloat16 th[32][33];
    __shared__ __nv_bfloat16 tl[32][33];
    int z = blockIdx.z;
    int b = z >> 5, h = z & 31;
    const size_t in_off  = (size_t)b * SEQ * H3 + 2 * HID + (size_t)h * HDIM;
    const size_t out_off = (size_t)z * HDIM * SEQ;
    int k0 = blockIdx.x * 32;   // token dim
    int d0 = blockIdx.y * 32;   // head dim
    int tx = threadIdx.x, ty = threadIdx.y;  // (32, 8)
#pragma unroll
    for (int i = 0; i < 32; i += 8) {
        size_t src = in_off + (size_t)(k0 + ty + i) * H3 + d0 + tx;
        th[ty + i][tx] = qh[src];
        tl[ty + i][tx] = ql[src];
    }
    __syncthreads();
#pragma unroll
    for (int i = 0; i < 32; i += 8) {
        size_t dst = out_off + (size_t)(d0 + ty + i) * SEQ + k0 + tx;
        vth[dst] = th[tx][ty + i];
        vtl[dst] = tl[tx][ty + i];
    }
}

// ================= causal softmax: fp32 scores -> split bf16 P =================
__global__ __launch_bounds__(256) void softmax_kernel(
    const float* __restrict__ scores, const float* __restrict__ mask,
    __nv_bfloat16* __restrict__ ph, __nv_bfloat16* __restrict__ pl)
{
    int q = blockIdx.x, h = blockIdx.y, b = blockIdx.z;
    const size_t rowoff = (((size_t)(b * NHEADS + h) * SEQ + q) * SEQ);
    const float* row = scores + rowoff;
    int tid = threadIdx.x;
    int c0 = tid * 4;

    float4 v  = *(const float4*)(row + c0);
    float4 mk = *(const float4*)(mask + b * SEQ + c0);
    float vals[4] = {v.x + mk.x, v.y + mk.y, v.z + mk.z, v.w + mk.w};
#pragma unroll
    for (int j = 0; j < 4; j++)
        if (c0 + j > q) vals[j] = -30000.0f;   // constant: robust to unwritten tiles

    float m = fmaxf(fmaxf(vals[0], vals[1]), fmaxf(vals[2], vals[3]));
#pragma unroll
    for (int off = 16; off > 0; off >>= 1)
        m = fmaxf(m, __shfl_xor_sync(0xffffffffu, m, off));

    __shared__ float rmax[8], rsum[8];
    __shared__ float s_max, s_inv;
    int wid = tid >> 5, lane = tid & 31;
    if (lane == 0) rmax[wid] = m;
    __syncthreads();
    if (tid == 0) {
        float t = rmax[0];
        for (int i = 1; i < 8; i++) t = fmaxf(t, rmax[i]);
        s_max = t;
    }
    __syncthreads();
    float rowmax = s_max;

    float e[4], sum = 0.f;
#pragma unroll
    for (int j = 0; j < 4; j++) { e[j] = __expf(vals[j] - rowmax); sum += e[j]; }
#pragma unroll
    for (int off = 16; off > 0; off >>= 1)
        sum += __shfl_xor_sync(0xffffffffu, sum, off);
    if (lane == 0) rsum[wid] = sum;
    __syncthreads();
    if (tid == 0) {
        float t = 0.f;
        for (int i = 0; i < 8; i++) t += rsum[i];
        s_inv = 1.f / t;
    }
    __syncthreads();
    float inv = s_inv;

    __nv_bfloat16 hh[4], ll[4];
#pragma unroll
    for (int j = 0; j < 4; j++) {
        float p = e[j] * inv;
        hh[j] = __float2bfloat16(p);
        ll[j] = __float2bfloat16(p - __bfloat162float(hh[j]));
    }
    *(uint2*)(ph + rowoff + c0) = *(uint2*)hh;
    *(uint2*)(pl + rowoff + c0) = *(uint2*)ll;
}

// ================= launch =================
extern "C" void kernel_launch(void* const* d_in, const int* in_sizes, int n_in,
                              void* d_out, int out_size)
{
    const float* x       = (const float*)d_in[0];
    const float* mask    = (const float*)d_in[1];
    const float* norm_w  = (const float*)d_in[2];
    const float* norm_b  = (const float*)d_in[3];
    const float* qkv_w   = (const float*)d_in[4];
    const float* qkv_b   = (const float*)d_in[5];
    const float* attn_ow = (const float*)d_in[6];
    float* out = (float*)d_out;

    __nv_bfloat16 *p_ah, *p_al, *p_wqh, *p_wql, *p_woh, *p_wol;
    __nv_bfloat16 *p_qh, *p_ql, *p_vth, *p_vtl, *p_ph, *p_pl, *p_ch, *p_cl;
    float *p_scores;
    cudaGetSymbolAddress((void**)&p_ah,  g_a_hi);
    cudaGetSymbolAddress((void**)&p_al,  g_a_lo);
    cudaGetSymbolAddress((void**)&p_wqh, g_wq_hi);
    cudaGetSymbolAddress((void**)&p_wql, g_wq_lo);
    cudaGetSymbolAddress((void**)&p_woh, g_wo_hi);
    cudaGetSymbolAddress((void**)&p_wol, g_wo_lo);
    cudaGetSymbolAddress((void**)&p_qh,  g_qkv_hi);
    cudaGetSymbolAddress((void**)&p_ql,  g_qkv_lo);
    cudaGetSymbolAddress((void**)&p_vth, g_vT_hi);
    cudaGetSymbolAddress((void**)&p_vtl, g_vT_lo);
    cudaGetSymbolAddress((void**)&p_ph,  g_p_hi);
    cudaGetSymbolAddress((void**)&p_pl,  g_p_lo);
    cudaGetSymbolAddress((void**)&p_ch,  g_c_hi);
    cudaGetSymbolAddress((void**)&p_cl,  g_c_lo);
    cudaGetSymbolAddress((void**)&p_scores, g_scores);

    cudaFuncSetAttribute((const void*)gemm_mma<true,  true,  false, false>, cudaFuncAttributeMaxDynamicSharedMemorySize, GM_SMEM);
    cudaFuncSetAttribute((const void*)gemm_mma<false, false, true,  false>, cudaFuncAttributeMaxDynamicSharedMemorySize, GM_SMEM);
    cudaFuncSetAttribute((const void*)gemm_mma<false, true,  false, true >, cudaFuncAttributeMaxDynamicSharedMemorySize, GM_SMEM);
    cudaFuncSetAttribute((const void*)gemm_mma<false, false, false, false>, cudaFuncAttributeMaxDynamicSharedMemorySize, GM_SMEM);

    const float inv_sqrt_hd = 0.08838834764831845f;  // 1/sqrt(128)

    // 1) LayerNorm -> split bf16 activations
    ln_split_kernel<<<TOKENS, 256>>>(x, norm_w, norm_b, p_ah, p_al);

    // 2) weight transpose+split to [N,K] bf16 hi/lo
    transpose_split_kernel<<<dim3(H3 / 32, HID / 32), dim3(32, 8)>>>(qkv_w, p_wqh, p_wql, HID, H3);
    transpose_split_kernel<<<dim3(HID / 32, HID / 32), dim3(32, 8)>>>(attn_ow, p_woh, p_wol, HID, HID);

    // 3) QKV GEMM + bias -> split bf16 qkv
    gemm_mma<true, true, false, false><<<dim3(TOKENS / 128, H3 / 128), 256, GM_SMEM>>>(
        p_ah, p_al, p_wqh, p_wql, qkv_b, nullptr, p_qh, p_ql,
        HID, HID, HID, H3,
        0, 0, 0, 0, 0, 0, 1.0f);

    // 4) transpose V -> vT [z][HD][S]
    transpose_v_kernel<<<dim3(SEQ / 32, HDIM / 32, BATCH * NHEADS), dim3(32, 8)>>>(
        p_qh, p_ql, p_vth, p_vtl);

    // 5) scores = Q @ K^T * 1/sqrt(hd), causal tile skip, fp32 out
    gemm_mma<false, false, true, false><<<dim3(SEQ / 128, SEQ / 128, BATCH * NHEADS), 256, GM_SMEM>>>(
        p_qh, p_ql, p_qh + HID, p_ql + HID, nullptr, p_scores, nullptr, nullptr,
        HDIM, H3, H3, SEQ,
        (long long)SEQ * H3, HDIM,
        (long long)SEQ * H3, HDIM,
        (long long)NHEADS * SEQ * SEQ, (long long)SEQ * SEQ,
        inv_sqrt_hd);

    // 6) softmax -> split bf16 P
    softmax_kernel<<<dim3(SEQ, NHEADS, BATCH), 256>>>(p_scores, mask, p_ph, p_pl);

    // 7) ctx = P @ V  (B = vT [HD,S]); causal K-limit; split bf16 out
    gemm_mma<false, true, false, true><<<dim3(SEQ / 128, HDIM / 128, BATCH * NHEADS), 256, GM_SMEM>>>(
        p_ph, p_pl, p_vth, p_vtl, nullptr, nullptr, p_ch, p_cl,
        SEQ, SEQ, SEQ, HID,
        (long long)NHEADS * SEQ * SEQ, (long long)SEQ * SEQ,
        (long long)NHEADS * HDIM * SEQ, (long long)HDIM * SEQ,
        (long long)SEQ * HID, HDIM,
        1.0f);

    // 8) out = ctx @ attn_ow, fp32
    gemm_mma<false, false, false, false><<<dim3(TOKENS / 128, HID / 128), 256, GM_SMEM>>>(
        p_ch, p_cl, p_woh, p_wol, nullptr, out, nullptr, nullptr,
        HID, HID, HID, HID,
        0, 0, 0, 0, 0, 0, 1.0f);
}

// round 9
// speedup vs baseline: 1.5953x; 1.4749x over previous
#include <cuda_runtime.h>
#include <cuda_bf16.h>
#include <cstdint>
#include <math.h>

#define HID    4096
#define NHEADS 32
#define HDIM   128
#define BATCH  2
#define SEQ    1024
#define TOKENS 2048
#define H3     12288

// ================= scratch (device globals; values stored as tf32-rounded fp32) =================
__device__ __align__(16) float g_a[(size_t)TOKENS * HID];
__device__ __align__(16) float g_wq[(size_t)H3 * HID];     // qkv_w^T [N,K]
__device__ __align__(16) float g_wo[(size_t)HID * HID];    // attn_ow^T [N,K]
__device__ __align__(16) float g_qkv[(size_t)TOKENS * H3];
__device__ __align__(16) float g_vT[(size_t)BATCH * NHEADS * HDIM * SEQ];
__device__ __align__(16) float g_scores[(size_t)BATCH * NHEADS * SEQ * SEQ];
__device__ __align__(16) float g_p[(size_t)BATCH * NHEADS * SEQ * SEQ];
__device__ __align__(16) float g_ctx[(size_t)TOKENS * HID];

// ================= helpers =================
__device__ __forceinline__ uint32_t smem_u32(const void* p) {
    uint32_t a;
    asm("{ .reg .u64 t; cvta.to.shared.u64 t, %1; cvt.u32.u64 %0, t; }" : "=r"(a) : "l"(p));
    return a;
}
__device__ __forceinline__ float tf32r(float x) {
    uint32_t r;
    asm("cvt.rna.tf32.f32 %0, %1;" : "=r"(r) : "f"(x));
    return __uint_as_float(r);
}
#define CP16(saddr, gptr) \
    asm volatile("cp.async.cg.shared.global [%0], [%1], 16;" :: "r"(saddr), "l"(gptr) : "memory")
#define CP_COMMIT() asm volatile("cp.async.commit_group;" ::: "memory")
#define CP_WAIT2()  asm volatile("cp.async.wait_group 2;" ::: "memory")
#define LDSM4(r0, r1, r2, r3, addr) \
    asm volatile("ldmatrix.sync.aligned.m8n8.x4.shared.b16 {%0,%1,%2,%3}, [%4];" \
        : "=r"(r0), "=r"(r1), "=r"(r2), "=r"(r3) : "r"(addr))
#define MMATF32(c, a, b0v, b1v) \
    asm volatile("mma.sync.aligned.m16n8k8.row.col.f32.tf32.tf32.f32 " \
        "{%0,%1,%2,%3}, {%4,%5,%6,%7}, {%8,%9}, {%0,%1,%2,%3};" \
        : "+f"((c)[0]), "+f"((c)[1]), "+f"((c)[2]), "+f"((c)[3]) \
        : "r"((a)[0]), "r"((a)[1]), "r"((a)[2]), "r"((a)[3]), "r"(b0v), "r"(b1v))

// ================= TF32 single-pass GEMM (3-stage cp.async, BK=32) =================
// C[M,N] = alpha * A[M,K] @ W[N,K]^T (+bias), A/W tf32-in-fp32, row strides lda/ldb.
// SMEM: 128B rows = 32 tf32 per row (one 32-K chunk), SW128 swizzle.
// tf32 m16n8k8 fragments == bf16 m16n8k16 fragments under the b16-pair view,
// so ldmatrix.x4.b16 addressing is unchanged from the bf16 engine.
// Tile 128x128, 8 warps (2m x 4n), warp tile 64x32. 2 CTAs/SM.
// CAUSAL: tile skip above diagonal. KLIM: K limited to (bm+1)*128 (causal PV).
// ROUND_OUT: round epilogue values to tf32 before storing.
#define GM_STAGE 32768
#define GM_BOFF  16384
#define GM_SMEM  (3 * GM_STAGE)   // 98304; 2 CTAs/SM (192KB of 228KB)

template<bool HAS_BIAS, bool ROUND_OUT, bool CAUSAL, bool KLIM>
__global__ __launch_bounds__(256, 2) void gemm_tf32(
    const float* __restrict__ A, const float* __restrict__ W,
    const float* __restrict__ bias, float* __restrict__ C,
    int K, int lda, int ldb, int ldc,
    long long sA1, long long sA2, long long sB1, long long sB2,
    long long sC1, long long sC2, float alpha)
{
    extern __shared__ char smem[];
    const int bm = blockIdx.x, bn = blockIdx.y;
    if (CAUSAL && bn > bm) return;

    const uint32_t sbase = smem_u32(smem);
    const int tid = threadIdx.x;
    const int wid = tid >> 5, lane = tid & 31;
    const int warp_m = wid >> 2, warp_n = wid & 3;

    const int z = blockIdx.z;
    const long long offA = (long long)(z >> 5) * sA1 + (long long)(z & 31) * sA2;
    const long long offB = (long long)(z >> 5) * sB1 + (long long)(z & 31) * sB2;
    const long long offC = (long long)(z >> 5) * sC1 + (long long)(z & 31) * sC2;

    const float* baseA = A + offA + (size_t)bm * 128 * lda;
    const float* baseB = W + offB + (size_t)bn * 128 * ldb;

    // loader: thread -> (row_base r, 16B unit u). unit u covers tf32 cols 4u..4u+3.
    const int r_base = tid >> 3;
    const int u = tid & 7;
    const int koff_u = u * 4;
    const uint32_t sw_u = (uint32_t)u * 16u;

#define LOAD_STAGE(st, k0elem) do { \
        const uint32_t _sb = sbase + (uint32_t)(st) * GM_STAGE; \
        _Pragma("unroll") \
        for (int _p = 0; _p < 4; _p++) { \
            const int _r = _p * 32 + r_base; \
            const uint32_t _sw = sw_u ^ (uint32_t)((_r & 7) << 4); \
            CP16(_sb + (uint32_t)_r * 128u + _sw, \
                 baseA + (size_t)_r * lda + (k0elem) + koff_u); \
            CP16(_sb + GM_BOFF + (uint32_t)_r * 128u + _sw, \
                 baseB + (size_t)_r * ldb + (k0elem) + koff_u); \
        } \
    } while (0)

    // ldmatrix lane addressing (b16 view: 16 rows x 16 b16-cols per x4 = k8 tf32)
    const int lr = lane & 15;
    const uint32_t kb_lane = (uint32_t)(lane >> 4) * 16u;
    uint32_t a_ro[4], a_xm[4];
#pragma unroll
    for (int mb = 0; mb < 4; mb++) {
        const int r = warp_m * 64 + mb * 16 + lr;
        a_ro[mb] = (uint32_t)r * 128u;
        a_xm[mb] = (uint32_t)((r & 7) << 4);
    }
    uint32_t b_ro[2], b_xm[2];
#pragma unroll
    for (int g = 0; g < 2; g++) {
        const int r = warp_n * 32 + g * 16 + lr;
        b_ro[g] = (uint32_t)r * 128u;
        b_xm[g] = (uint32_t)((r & 7) << 4);
    }

    float acc[4][4][4] = {};

    int Keff = K;
    if (KLIM) { int kl = (bm + 1) * 128; Keff = kl < K ? kl : K; }
    const int NC = Keff / 32;

    LOAD_STAGE(0, 0);  CP_COMMIT();
    LOAD_STAGE(1, 32); CP_COMMIT();

    for (int i = 0; i < NC; i++) {
        if (i + 2 < NC) LOAD_STAGE((i + 2) % 3, (size_t)(i + 2) * 32);
        CP_COMMIT();
        CP_WAIT2();
        __syncthreads();

        const uint32_t sb = sbase + (uint32_t)(i % 3) * GM_STAGE;
#pragma unroll
        for (int ks = 0; ks < 4; ks++) {           // 4 x k8 per 32-K chunk
            const uint32_t kb = (uint32_t)ks * 32u + kb_lane;
            uint32_t af[4][4];
#pragma unroll
            for (int mb = 0; mb < 4; mb++) {
                LDSM4(af[mb][0], af[mb][1], af[mb][2], af[mb][3],
                      sb + a_ro[mb] + (kb ^ a_xm[mb]));
            }
            uint32_t bf[2][4];
#pragma unroll
            for (int g = 0; g < 2; g++) {
                LDSM4(bf[g][0], bf[g][1], bf[g][2], bf[g][3],
                      sb + GM_BOFF + b_ro[g] + (kb ^ b_xm[g]));
            }
#pragma unroll
            for (int mb = 0; mb < 4; mb++) {
#pragma unroll
                for (int nf = 0; nf < 4; nf++) {
                    const int g = nf >> 1, j = nf & 1;
                    MMATF32(acc[mb][nf], af[mb], bf[g][j], bf[g][2 + j]);
                }
            }
        }
        __syncthreads();
    }

    // epilogue
    const int qrow = lane >> 2;
    const int qcol = (lane & 3) * 2;
#pragma unroll
    for (int mb = 0; mb < 4; mb++) {
        const int m0 = bm * 128 + warp_m * 64 + mb * 16 + qrow;
#pragma unroll
        for (int nf = 0; nf < 4; nf++) {
            const int n0 = bn * 128 + warp_n * 32 + nf * 8 + qcol;
            float b0 = 0.f, b1 = 0.f;
            if (HAS_BIAS) { b0 = bias[n0]; b1 = bias[n0 + 1]; }
            float v00 = acc[mb][nf][0] * alpha + b0;
            float v01 = acc[mb][nf][1] * alpha + b1;
            float v10 = acc[mb][nf][2] * alpha + b0;
            float v11 = acc[mb][nf][3] * alpha + b1;
            if (ROUND_OUT) {
                v00 = tf32r(v00); v01 = tf32r(v01);
                v10 = tf32r(v10); v11 = tf32r(v11);
            }
            float2 r0, r1;
            r0.x = v00; r0.y = v01;
            r1.x = v10; r1.y = v11;
            *(float2*)(C + offC + (size_t)m0 * ldc + n0)       = r0;
            *(float2*)(C + offC + (size_t)(m0 + 8) * ldc + n0) = r1;
        }
    }
#undef LOAD_STAGE
}

// ================= LayerNorm -> tf32-rounded fp32 =================
__global__ __launch_bounds__(256) void ln_kernel(
    const float* __restrict__ x, const float* __restrict__ w,
    const float* __restrict__ bvec, float* __restrict__ o)
{
    int row = blockIdx.x;
    int tid = threadIdx.x;
    const float* xr = x + (size_t)row * HID;
    float4 v[4];
    float sum = 0.f, ss = 0.f;
#pragma unroll
    for (int i = 0; i < 4; i++) {
        v[i] = *(const float4*)(xr + (i * 256 + tid) * 4);
        sum += v[i].x + v[i].y + v[i].z + v[i].w;
        ss  += v[i].x * v[i].x + v[i].y * v[i].y + v[i].z * v[i].z + v[i].w * v[i].w;
    }
#pragma unroll
    for (int off = 16; off > 0; off >>= 1) {
        sum += __shfl_xor_sync(0xffffffffu, sum, off);
        ss  += __shfl_xor_sync(0xffffffffu, ss,  off);
    }
    __shared__ float r0[8], r1[8];
    __shared__ float s_mu, s_rstd;
    int wid = tid >> 5, lane = tid & 31;
    if (lane == 0) { r0[wid] = sum; r1[wid] = ss; }
    __syncthreads();
    if (tid == 0) {
        float s = 0.f, q = 0.f;
        for (int i = 0; i < 8; i++) { s += r0[i]; q += r1[i]; }
        float mu  = s * (1.f / HID);
        float var = q * (1.f / HID) - mu * mu;
        s_mu = mu; s_rstd = rsqrtf(var + 1e-5f);
    }
    __syncthreads();
    float mu = s_mu, rstd = s_rstd;
#pragma unroll
    for (int i = 0; i < 4; i++) {
        int c = (i * 256 + tid) * 4;
        float4 wv = *(const float4*)(w + c);
        float4 bv = *(const float4*)(bvec + c);
        float4 ov;
        ov.x = tf32r((v[i].x - mu) * rstd * wv.x + bv.x);
        ov.y = tf32r((v[i].y - mu) * rstd * wv.y + bv.y);
        ov.z = tf32r((v[i].z - mu) * rstd * wv.z + bv.z);
        ov.w = tf32r((v[i].w - mu) * rstd * wv.w + bv.w);
        *(float4*)(o + (size_t)row * HID + c) = ov;
    }
}

// ================= transpose + round: in[K,N] f32 -> out[N,K] tf32 =================
__global__ __launch_bounds__(256) void transpose_round_kernel(
    const float* __restrict__ in, float* __restrict__ o, int Kdim, int Ndim)
{
    __shared__ float tile[32][33];
    int n0 = blockIdx.x * 32, k0 = blockIdx.y * 32;
    int tx = threadIdx.x, ty = threadIdx.y;   // block (32,8)
#pragma unroll
    for (int i = 0; i < 32; i += 8)
        tile[ty + i][tx] = in[(size_t)(k0 + ty + i) * Ndim + n0 + tx];
    __syncthreads();
#pragma unroll
    for (int i = 0; i < 32; i += 8)
        o[(size_t)(n0 + ty + i) * Kdim + k0 + tx] = tf32r(tile[tx][ty + i]);
}

// ================= batched transpose of V: [S,HD] (stride H3) -> [HD,S] =================
__global__ __launch_bounds__(256) void transpose_v_kernel(
    const float* __restrict__ qkv, float* __restrict__ vt)
{
    __shared__ float tile[32][33];
    int z = blockIdx.z;
    int b = z >> 5, h = z & 31;
    const size_t in_off  = (size_t)b * SEQ * H3 + 2 * HID + (size_t)h * HDIM;
    const size_t out_off = (size_t)z * HDIM * SEQ;
    int k0 = blockIdx.x * 32;   // token dim
    int d0 = blockIdx.y * 32;   // head dim
    int tx = threadIdx.x, ty = threadIdx.y;  // (32, 8)
#pragma unroll
    for (int i = 0; i < 32; i += 8)
        tile[ty + i][tx] = qkv[in_off + (size_t)(k0 + ty + i) * H3 + d0 + tx];
    __syncthreads();
#pragma unroll
    for (int i = 0; i < 32; i += 8)
        vt[out_off + (size_t)(d0 + ty + i) * SEQ + k0 + tx] = tile[tx][ty + i];
}

// ================= causal softmax: fp32 scores -> tf32 P =================
__global__ __launch_bounds__(256) void softmax_kernel(
    const float* __restrict__ scores, const float* __restrict__ mask,
    float* __restrict__ p)
{
    int q = blockIdx.x, h = blockIdx.y, b = blockIdx.z;
    const size_t rowoff = (((size_t)(b * NHEADS + h) * SEQ + q) * SEQ);
    const float* row = scores + rowoff;
    int tid = threadIdx.x;
    int c0 = tid * 4;

    float4 v  = *(const float4*)(row + c0);
    float4 mk = *(const float4*)(mask + b * SEQ + c0);
    float vals[4] = {v.x + mk.x, v.y + mk.y, v.z + mk.z, v.w + mk.w};
#pragma unroll
    for (int j = 0; j < 4; j++)
        if (c0 + j > q) vals[j] = -30000.0f;   // constant: robust to unwritten tiles

    float m = fmaxf(fmaxf(vals[0], vals[1]), fmaxf(vals[2], vals[3]));
#pragma unroll
    for (int off = 16; off > 0; off >>= 1)
        m = fmaxf(m, __shfl_xor_sync(0xffffffffu, m, off));

    __shared__ float rmax[8], rsum[8];
    __shared__ float s_max, s_inv;
    int wid = tid >> 5, lane = tid & 31;
    if (lane == 0) rmax[wid] = m;
    __syncthreads();
    if (tid == 0) {
        float t = rmax[0];
        for (int i = 1; i < 8; i++) t = fmaxf(t, rmax[i]);
        s_max = t;
    }
    __syncthreads();
    float rowmax = s_max;

    float e[4], sum = 0.f;
#pragma unroll
    for (int j = 0; j < 4; j++) { e[j] = __expf(vals[j] - rowmax); sum += e[j]; }
#pragma unroll
    for (int off = 16; off > 0; off >>= 1)
        sum += __shfl_xor_sync(0xffffffffu, sum, off);
    if (lane == 0) rsum[wid] = sum;
    __syncthreads();
    if (tid == 0) {
        float t = 0.f;
        for (int i = 0; i < 8; i++) t += rsum[i];
        s_inv = 1.f / t;
    }
    __syncthreads();
    float inv = s_inv;

    float4 o;
    o.x = tf32r(e[0] * inv);
    o.y = tf32r(e[1] * inv);
    o.z = tf32r(e[2] * inv);
    o.w = tf32r(e[3] * inv);
    *(float4*)(p + rowoff + c0) = o;
}

// ================= launch =================
extern "C" void kernel_launch(void* const* d_in, const int* in_sizes, int n_in,
                              void* d_out, int out_size)
{
    const float* x       = (const float*)d_in[0];
    const float* mask    = (const float*)d_in[1];
    const float* norm_w  = (const float*)d_in[2];
    const float* norm_b  = (const float*)d_in[3];
    const float* qkv_w   = (const float*)d_in[4];
    const float* qkv_b   = (const float*)d_in[5];
    const float* attn_ow = (const float*)d_in[6];
    float* out = (float*)d_out;

    float *p_a, *p_wq, *p_wo, *p_qkv, *p_vt, *p_scores, *p_p, *p_ctx;
    cudaGetSymbolAddress((void**)&p_a,   g_a);
    cudaGetSymbolAddress((void**)&p_wq,  g_wq);
    cudaGetSymbolAddress((void**)&p_wo,  g_wo);
    cudaGetSymbolAddress((void**)&p_qkv, g_qkv);
    cudaGetSymbolAddress((void**)&p_vt,  g_vT);
    cudaGetSymbolAddress((void**)&p_scores, g_scores);
    cudaGetSymbolAddress((void**)&p_p,   g_p);
    cudaGetSymbolAddress((void**)&p_ctx, g_ctx);

    cudaFuncSetAttribute((const void*)gemm_tf32<true,  true,  false, false>, cudaFuncAttributeMaxDynamicSharedMemorySize, GM_SMEM);
    cudaFuncSetAttribute((const void*)gemm_tf32<false, false, true,  false>, cudaFuncAttributeMaxDynamicSharedMemorySize, GM_SMEM);
    cudaFuncSetAttribute((const void*)gemm_tf32<false, true,  false, true >, cudaFuncAttributeMaxDynamicSharedMemorySize, GM_SMEM);
    cudaFuncSetAttribute((const void*)gemm_tf32<false, false, false, false>, cudaFuncAttributeMaxDynamicSharedMemorySize, GM_SMEM);

    const float inv_sqrt_hd = 0.08838834764831845f;  // 1/sqrt(128)

    // 1) LayerNorm -> tf32 activations
    ln_kernel<<<TOKENS, 256>>>(x, norm_w, norm_b, p_a);

    // 2) weight transpose+round to [N,K] tf32
    transpose_round_kernel<<<dim3(H3 / 32, HID / 32), dim3(32, 8)>>>(qkv_w, p_wq, HID, H3);
    transpose_round_kernel<<<dim3(HID / 32, HID / 32), dim3(32, 8)>>>(attn_ow, p_wo, HID, HID);

    // 3) QKV GEMM + bias -> tf32 qkv
    gemm_tf32<true, true, false, false><<<dim3(TOKENS / 128, H3 / 128), 256, GM_SMEM>>>(
        p_a, p_wq, qkv_b, p_qkv,
        HID, HID, HID, H3,
        0, 0, 0, 0, 0, 0, 1.0f);

    // 4) transpose V -> vT [z][HD][S]
    transpose_v_kernel<<<dim3(SEQ / 32, HDIM / 32, BATCH * NHEADS), dim3(32, 8)>>>(p_qkv, p_vt);

    // 5) scores = Q @ K^T * 1/sqrt(hd), causal tile skip, fp32 out
    gemm_tf32<false, false, true, false><<<dim3(SEQ / 128, SEQ / 128, BATCH * NHEADS), 256, GM_SMEM>>>(
        p_qkv, p_qkv + HID, nullptr, p_scores,
        HDIM, H3, H3, SEQ,
        (long long)SEQ * H3, HDIM,
        (long long)SEQ * H3, HDIM,
        (long long)NHEADS * SEQ * SEQ, (long long)SEQ * SEQ,
        inv_sqrt_hd);

    // 6) softmax -> tf32 P
    softmax_kernel<<<dim3(SEQ, NHEADS, BATCH), 256>>>(p_scores, mask, p_p);

    // 7) ctx = P @ V  (B = vT [HD,S]); causal K-limit; tf32 out in [b,s,h*hd] layout
    gemm_tf32<false, true, false, true><<<dim3(SEQ / 128, HDIM / 128, BATCH * NHEADS), 256, GM_SMEM>>>(
        p_p, p_vt, nullptr, p_ctx,
        SEQ, SEQ, SEQ, HID,
        (long long)NHEADS * SEQ * SEQ, (long long)SEQ * SEQ,
        (long long)NHEADS * HDIM * SEQ, (long long)HDIM * SEQ,
        (long long)SEQ * HID, HDIM,
        1.0f);

    // 8) out = ctx @ attn_ow, fp32
    gemm_tf32<false, false, false, false><<<dim3(TOKENS / 128, HID / 128), 256, GM_SMEM>>>(
        p_ctx, p_wo, nullptr, out,
        HID, HID, HID, HID,
        0, 0, 0, 0, 0, 0, 1.0f);
}